// round 6
// baseline (speedup 1.0000x reference)
#include <cuda_runtime.h>

// Problem constants
#define SEQ      1024
#define BATCH    64
#define IN_DIM   128
#define HID      512
#define ALPHA    0.1f
#define SBH      (BATCH * HID)   // 32768 elements per timestep

// ---------------- persistent recurrent kernel config ----------------
#define R_GRID    128            // must be co-resident (<= 148/152 SMs, 1 CTA/SM fits easily)
#define R_THREADS 256
#define HG        32             // h-groups (512 / 16)
#define BG        4              // b-groups (64 / 16)
#define H_C       16             // h per CTA
#define B_C       16             // b per CTA

// fr double buffer (L2-resident, 256 KB) + barrier state
__device__ float g_fr[2][SBH];
__device__ volatile unsigned g_flags[R_GRID];
__device__ volatile unsigned g_release;

// ---------------------------------------------------------------
// Reset kernel: zero fr buffers and barrier state (per launch,
// keeps kernel_launch deterministic across graph replays)
// ---------------------------------------------------------------
__global__ void reset_kernel() {
    int tid = blockIdx.x * blockDim.x + threadIdx.x;
    float* p = (float*)g_fr;
    for (int i = tid; i < 2 * SBH; i += gridDim.x * blockDim.x) p[i] = 0.0f;
    if (blockIdx.x == 0) {
        if (threadIdx.x < R_GRID) g_flags[threadIdx.x] = 0u;
        if (threadIdx.x == 0) g_release = 0u;
    }
}

// ---------------------------------------------------------------
// Input projection GEMM:
//   out[m][n] = ALPHA * ( sum_k inp[m][k] * Win[n][k] + b_in[n] + b_hid[n] )
// m = s*64+b (65536 rows), n = hidden (512), K = 128.
// Tiled 64x64, BK=32, thread tile 4x4, k-major smem with pad.
// Writes directly into d_out, which the recurrent kernel consumes
// in-place and overwrites with fr_t.
// ---------------------------------------------------------------
#define BM 64
#define BN 64
#define BK 32
#define TPAD 4

__global__ __launch_bounds__(256) void uproj_kernel(
    const float* __restrict__ inp, const float* __restrict__ Win,
    const float* __restrict__ b_in, const float* __restrict__ b_hid,
    float* __restrict__ out)
{
    __shared__ __align__(16) float As[BK][BM + TPAD];  // [k][m], row = 68 floats (272B, 16-aligned)
    __shared__ __align__(16) float Bs[BK][BN + TPAD];  // [k][n]

    const int tid = threadIdx.x;
    const int m0 = (int)(blockIdx.x >> 3) * BM;
    const int n0 = (int)(blockIdx.x & 7) * BN;
    const int tx = tid & 15;
    const int ty = tid >> 4;

    const float4* A4 = (const float4*)inp;   // [65536][32] float4
    const float4* B4 = (const float4*)Win;   // [512][32] float4

    float acc[4][4];
    #pragma unroll
    for (int i = 0; i < 4; i++)
        #pragma unroll
        for (int j = 0; j < 4; j++) acc[i][j] = 0.0f;

    for (int kc = 0; kc < IN_DIM / BK; kc++) {
        #pragma unroll
        for (int t = 0; t < 2; t++) {
            int j = tid + 256 * t;          // 0..511 float4s of 64x32 tile
            int m  = j >> 3;
            int kq = j & 7;
            float4 va = A4[(m0 + m) * 32 + kc * 8 + kq];
            As[kq * 4 + 0][m] = va.x; As[kq * 4 + 1][m] = va.y;
            As[kq * 4 + 2][m] = va.z; As[kq * 4 + 3][m] = va.w;
            float4 vb = B4[(n0 + m) * 32 + kc * 8 + kq];
            Bs[kq * 4 + 0][m] = vb.x; Bs[kq * 4 + 1][m] = vb.y;
            Bs[kq * 4 + 2][m] = vb.z; Bs[kq * 4 + 3][m] = vb.w;
        }
        __syncthreads();
        #pragma unroll
        for (int k = 0; k < BK; k++) {
            float4 a = *(const float4*)&As[k][ty * 4];
            float4 b = *(const float4*)&Bs[k][tx * 4];
            float av[4] = {a.x, a.y, a.z, a.w};
            float bv[4] = {b.x, b.y, b.z, b.w};
            #pragma unroll
            for (int i = 0; i < 4; i++)
                #pragma unroll
                for (int j2 = 0; j2 < 4; j2++)
                    acc[i][j2] += av[i] * bv[j2];
        }
        __syncthreads();
    }

    const int n = n0 + tx * 4;
    float bias0 = b_in[n + 0] + b_hid[n + 0];
    float bias1 = b_in[n + 1] + b_hid[n + 1];
    float bias2 = b_in[n + 2] + b_hid[n + 2];
    float bias3 = b_in[n + 3] + b_hid[n + 3];
    #pragma unroll
    for (int i = 0; i < 4; i++) {
        int m = m0 + ty * 4 + i;
        float4 o;
        o.x = ALPHA * (acc[i][0] + bias0);
        o.y = ALPHA * (acc[i][1] + bias1);
        o.z = ALPHA * (acc[i][2] + bias2);
        o.w = ALPHA * (acc[i][3] + bias3);
        *(float4*)&out[m * HID + n] = o;
    }
}

// ---------------------------------------------------------------
// Persistent recurrent kernel.
// CTA owns a 16h x 16b output tile; W_hid rows for its 16 h live in
// smem for the whole kernel (32 KB). Each step: stage the 16-batch
// fr slice (16 KB) from the L2-resident double buffer into smem,
// compute the 512-dot per output, leaky-update v (in a register),
// relu, write state to d_out and fr to the other buffer, then a
// flag-based grid barrier (no atomic contention).
// ---------------------------------------------------------------
__global__ void __launch_bounds__(R_THREADS) rnn_kernel(
    const float* __restrict__ W_hid, float* __restrict__ out)
{
    extern __shared__ float4 smem[];
    float4* Wsm  = smem;              // [128][16] : idx = kq*16 + hl (32 KB)
    float4* frsm = smem + 128 * 16;   // [16][129] : idx = bl*129 + kq (padded, 33 KB)

    const int tid = threadIdx.x;
    const int bid = blockIdx.x;
    const int hg  = bid % HG;
    const int bg  = bid / HG;
    const int h0  = hg * H_C;
    const int b0  = bg * B_C;
    const int hl  = tid & (H_C - 1);  // output h within tile
    const int bl  = tid >> 4;         // output b within tile

    // Load this CTA's W_hid tile once (coalesced global reads).
    const float4* Wg = (const float4*)W_hid;  // [512][128] float4
    #pragma unroll
    for (int r = 0; r < 8; r++) {
        int idx = tid + 256 * r;      // 0..2047 (16 h * 128 kq)
        int wh  = idx >> 7;
        int kq  = idx & 127;
        Wsm[kq * 16 + wh] = Wg[(h0 + wh) * 128 + kq];
    }

    const int out_off = (b0 + bl) * HID + h0 + hl;
    const float4* frow = frsm + bl * 129;
    const float4* wrow = Wsm + hl;

    float v = 0.0f;

    for (int t = 0; t < SEQ; t++) {
        // Stage fr_{t-1} slice for our 16 batches (L2 -> smem, bypass L1).
        const float4* src = (const float4*)g_fr[t & 1] + b0 * (HID / 4);
        #pragma unroll
        for (int r = 0; r < 8; r++) {
            int idx = tid + 256 * r;  // 0..2047 (16 b * 128 kq)
            int sb  = idx >> 7;
            int kq  = idx & 127;
            frsm[sb * 129 + kq] = __ldcg(src + sb * 128 + kq);
        }
        // Prefetch the precomputed input term (streams from DRAM, long latency
        // hidden behind the dot-product loop).
        float cval = out[t * SBH + out_off];
        __syncthreads();

        // 512-element dot: fr[b, :] . W_hid[h, :]
        float ax = 0.f, ay = 0.f, az = 0.f, aw = 0.f;
        #pragma unroll 8
        for (int kq = 0; kq < 128; kq++) {
            float4 w = wrow[kq * 16];   // 256B/warp, 2-way dedup, conflict-free
            float4 f = frow[kq];        // 2 addrs/warp, disjoint banks (129 pad)
            ax += w.x * f.x;
            ay += w.y * f.y;
            az += w.z * f.z;
            aw += w.w * f.w;
        }
        v = 0.9f * v + ALPHA * ((ax + ay) + (az + aw)) + cval;
        float fr = fmaxf(v, 0.0f);

        out[t * SBH + out_off] = fr;                    // state output (overwrites cval slot)
        __stcg(&g_fr[(t + 1) & 1][out_off], fr);        // publish to L2 for next step

        // ---------------- grid barrier, phase t+1 ----------------
        __threadfence();      // make this thread's fr write device-visible
        __syncthreads();      // all threads of CTA fenced before signaling
        unsigned ph = (unsigned)(t + 1);
        if (bid == 0) {
            if (tid >= 1 && tid < R_GRID) {
                while (g_flags[tid] < ph) { }           // one flag per CTA, no contention
            }
            __syncthreads();
            if (tid == 0) {
                __threadfence();
                g_release = ph;
            }
        } else {
            if (tid == 0) {
                g_flags[bid] = ph;
                while (g_release < ph) { }
            }
        }
        __syncthreads();
    }
}

// ---------------------------------------------------------------
// Launch
// ---------------------------------------------------------------
extern "C" void kernel_launch(void* const* d_in, const int* in_sizes, int n_in,
                              void* d_out, int out_size) {
    (void)in_sizes; (void)n_in; (void)out_size;
    const float* inp   = (const float*)d_in[0];   // (1024, 64, 128)
    const float* W_in  = (const float*)d_in[1];   // (512, 128)
    const float* b_in  = (const float*)d_in[2];   // (512,)
    const float* W_hid = (const float*)d_in[3];   // (512, 512)
    const float* b_hid = (const float*)d_in[4];   // (512,)
    float* out = (float*)d_out;                   // (1024, 64, 512)

    reset_kernel<<<64, 256>>>();

    // u-proj GEMM: 65536x512, tiles 64x64 -> grid 1024*8
    uproj_kernel<<<8192, 256>>>(inp, W_in, b_in, b_hid, out);

    // Persistent recurrent kernel: 65792 B dynamic smem
    cudaFuncSetAttribute(rnn_kernel, cudaFuncAttributeMaxDynamicSharedMemorySize, 65792);
    rnn_kernel<<<R_GRID, R_THREADS, 65792>>>(W_hid, out);
}